// round 12
// baseline (speedup 1.0000x reference)
#include <cuda_runtime.h>
#include <cuda_bf16.h>
#include <math.h>
#include <stdint.h>

#define NPROP 1000
#define MPAD  1024
#define FM_HW 10000
#define K1    12544
#define HID   1024
#define MAXDET 100

typedef __nv_bfloat16 bf;
typedef unsigned long long ull;

// ---------------- scratch ----------------
__device__ float g_fmT[FM_HW * 256];
__device__ bf g_A0[MPAD*K1], g_A1[MPAD*K1];
__device__ bf g_W10[HID*K1], g_W11[HID*K1];
__device__ bf g_X1a[MPAD*HID], g_X1b[MPAD*HID];
__device__ bf g_W20[HID*HID], g_W21[HID*HID];
__device__ bf g_X2a[MPAD*HID], g_X2b[MPAD*HID];
__device__ bf g_WH0[128*HID], g_WH1[128*HID];
__device__ float g_bh[128];
__device__ float g_part[4 * MPAD * HID];
__device__ float g_head[NPROP * 105];
__device__ float  g_candC[20*1000];
__device__ float4 g_boxesC[20*1000], g_boxoffC[20*1000];
__device__ float  g_svS[20*MAXDET];
__device__ int    g_svOrd[20*MAXDET];
__device__ float4 g_svBox[20*MAXDET];
__device__ int    g_svCnt[20];

// ---------------- PTX helpers ----------------
__device__ __forceinline__ uint32_t s2u(const void* p){
    uint32_t a; asm("{ .reg .u64 t; cvta.to.shared.u64 t, %1; cvt.u32.u64 %0, t; }":"=r"(a):"l"(p)); return a;
}
__device__ __forceinline__ void cpa16(uint32_t s, const void* g){
    asm volatile("cp.async.cg.shared.global [%0], [%1], 16;"::"r"(s),"l"(g):"memory");
}
__device__ __forceinline__ void ldsm4(uint32_t* r, uint32_t addr){
    asm volatile("ldmatrix.sync.aligned.m8n8.x4.shared.b16 {%0,%1,%2,%3}, [%4];"
        :"=r"(r[0]),"=r"(r[1]),"=r"(r[2]),"=r"(r[3]):"r"(addr));
}
__device__ __forceinline__ void mma16816(float* d, const uint32_t* a, const uint32_t* b){
    asm volatile("mma.sync.aligned.m16n8k16.row.col.f32.bf16.bf16.f32 "
        "{%0,%1,%2,%3}, {%4,%5,%6,%7}, {%8,%9}, {%0,%1,%2,%3};"
        :"+f"(d[0]),"+f"(d[1]),"+f"(d[2]),"+f"(d[3])
        :"r"(a[0]),"r"(a[1]),"r"(a[2]),"r"(a[3]),"r"(b[0]),"r"(b[1]));
}
__device__ __forceinline__ void split2(float v, bf& b0, bf& b1){
    b0 = __float2bfloat16(v);
    b1 = __float2bfloat16(v - __bfloat162float(b0));
}

// ---------------- w1 transpose + permute + split ----------------
__global__ void conv_T_perm(const float* __restrict__ in,
                            bf* __restrict__ o0, bf* __restrict__ o1){
    __shared__ float tl[32][33];
    int bx = blockIdx.x;
    int cell = bx >> 3, c0 = (bx & 7) * 32;
    int h0 = blockIdx.y * 32;
    int tx = threadIdx.x, ty = threadIdx.y;
#pragma unroll
    for (int j = 0; j < 32; j += 8){
        int c = c0 + ty + j;
        int r = c * 49 + cell;
        tl[ty+j][tx] = in[(size_t)r * HID + h0 + tx];
    }
    __syncthreads();
#pragma unroll
    for (int j = 0; j < 32; j += 8){
        int h = h0 + ty + j;
        float v = tl[tx][ty+j];
        size_t o = (size_t)h * K1 + cell*256 + c0 + tx;
        bf h0b, h1b; split2(v, h0b, h1b);
        o0[o] = h0b; o1[o] = h1b;
    }
}

// ---------------- plain transpose + split ----------------
__global__ void conv_T(const float* __restrict__ in, int R, int C,
                       bf* __restrict__ o0, bf* __restrict__ o1){
    __shared__ float tl[32][33];
    int r0 = blockIdx.y*32, c0 = blockIdx.x*32, tx = threadIdx.x, ty = threadIdx.y;
#pragma unroll
    for (int j = 0; j < 32; j += 8)
        tl[ty+j][tx] = in[(size_t)(r0+ty+j)*C + c0 + tx];
    __syncthreads();
#pragma unroll
    for (int j = 0; j < 32; j += 8){
        float v = tl[tx][ty+j];
        size_t o = (size_t)(c0+ty+j)*R + r0 + tx;
        bf h0, h1; split2(v, h0, h1);
        o0[o] = h0; o1[o] = h1;
    }
}

// ---------------- transpose FM ----------------
__global__ void transpose_fm(const float* __restrict__ fm){
    __shared__ float tl[32][33];
    int hw0 = blockIdx.x*32, c0 = blockIdx.y*32, tx = threadIdx.x, ty = threadIdx.y;
#pragma unroll
    for (int j = 0; j < 32; j += 8){
        int hw = hw0 + tx;
        tl[ty+j][tx] = (hw < FM_HW) ? fm[(c0+ty+j)*FM_HW + hw] : 0.f;
    }
    __syncthreads();
#pragma unroll
    for (int j = 0; j < 32; j += 8){
        int hw = hw0 + ty + j;
        if (hw < FM_HW) g_fmT[hw*256 + c0 + tx] = tl[tx][ty+j];
    }
}

// ---------------- ROI align -> split-bf16 A ----------------
__global__ void roi_align_kernel(const float* __restrict__ rois){
    int n = blockIdx.x, t = threadIdx.x;
    int tc = t & 63, cg = t >> 6;
    float4 r = ((const float4*)rois)[n];
    float b0 = r.x*0.125f - 0.5f, b1 = r.y*0.125f - 0.5f;
    float bw = (r.z*0.125f - 0.5f - b0) / 7.0f, bh = (r.w*0.125f - 0.5f - b1) / 7.0f;
    __shared__ int sx0[14], sx1[14], sy0[14], sy1[14];
    __shared__ float swx0[14], swx1[14], swy0[14], swy1[14], svx[14], svy[14];
    if (t < 14){
        int p = t >> 1, s = t & 1;
        float off = (float)p + ((float)s + 0.5f)*0.5f;
        float v = b0 + off*bw;
        svx[t] = (v >= -1.f && v <= 100.f) ? 1.f : 0.f;
        v = fminf(fmaxf(v, 0.f), 99.f);
        float v0 = floorf(v); int i0 = (int)v0;
        sx0[t] = i0; sx1[t] = min(i0+1, 99); swx1[t] = v - v0; swx0[t] = 1.f - (v - v0);
        v = b1 + off*bh;
        svy[t] = (v >= -1.f && v <= 100.f) ? 1.f : 0.f;
        v = fminf(fmaxf(v, 0.f), 99.f);
        v0 = floorf(v); i0 = (int)v0;
        sy0[t] = i0; sy1[t] = min(i0+1, 99); swy1[t] = v - v0; swy0[t] = 1.f - (v - v0);
    }
    __syncthreads();
    const float4* fmT4 = (const float4*)g_fmT;
    bf* a0p = g_A0 + (size_t)n*K1;
    bf* a1p = g_A1 + (size_t)n*K1;
    for (int cell = cg; cell < 49; cell += 4){
        int ph = cell / 7, pw = cell - ph*7;
        float ax = 0, ay = 0, az = 0, aw = 0;
#pragma unroll
        for (int sy = 0; sy < 2; sy++){
            int j = ph*2 + sy;
            int y0 = sy0[j], y1 = sy1[j];
            float wy0 = swy0[j], wy1 = swy1[j], vy = svy[j];
#pragma unroll
            for (int sx = 0; sx < 2; sx++){
                int k = pw*2 + sx;
                if (vy * svx[k] != 0.f){
                    int x0 = sx0[k], x1 = sx1[k];
                    float w00 = wy0*swx0[k], w01 = wy0*swx1[k], w10 = wy1*swx0[k], w11 = wy1*swx1[k];
                    float4 f00 = fmT4[(y0*100+x0)*64+tc], f01 = fmT4[(y0*100+x1)*64+tc];
                    float4 f10 = fmT4[(y1*100+x0)*64+tc], f11 = fmT4[(y1*100+x1)*64+tc];
                    ax += w00*f00.x + w01*f01.x + w10*f10.x + w11*f11.x;
                    ay += w00*f00.y + w01*f01.y + w10*f10.y + w11*f11.y;
                    az += w00*f00.z + w01*f01.z + w10*f10.z + w11*f11.z;
                    aw += w00*f00.w + w01*f01.w + w10*f10.w + w11*f11.w;
                }
            }
        }
        float vals[4] = {ax*0.25f, ay*0.25f, az*0.25f, aw*0.25f};
        bf p0[4], p1[4];
#pragma unroll
        for (int i = 0; i < 4; i++) split2(vals[i], p0[i], p1[i]);
        int base = cell*256 + tc*4;
        *(ull*)(a0p + base) = *(ull*)p0;
        *(ull*)(a1p + base) = *(ull*)p1;
    }
}

// ---------------- heads weights ----------------
__global__ void conv_heads(const float* __restrict__ wc, const float* __restrict__ bc,
                           const float* __restrict__ wb, const float* __restrict__ bb){
    int h = blockIdx.x;
    for (int k = threadIdx.x; k < HID; k += 256){
        float v = (h < 21) ? wc[k*21 + h] : ((h < 105) ? wb[k*84 + (h-21)] : 0.f);
        bf h0, h1; split2(v, h0, h1);
        size_t o = (size_t)h*HID + k;
        g_WH0[o] = h0; g_WH1[o] = h1;
    }
    if (threadIdx.x == 0)
        g_bh[h] = (h < 21) ? bc[h] : ((h < 105) ? bb[h-21] : 0.f);
}

// ---------------- mma.sync bf16 GEMM (split-2, 3 terms), 4-deep 16k stages ------
// sync once per 32k (pair of stages). smem 96KB/CTA -> 2 CTAs/SM.
#define TP    48
#define TILEB (128*TP)           // 6144
#define HBUF  (4*TILEB)          // 24576 per 16-k stage
#define GSMEM (4*HBUF)           // 98304

__global__ __launch_bounds__(256, 2)
void gemm_mma(const bf* __restrict__ A0, const bf* __restrict__ A1,
              const bf* __restrict__ B0, const bf* __restrict__ B1,
              const float* __restrict__ bias, int K, int mode,
              float* __restrict__ Cp, float* __restrict__ Oh){
    extern __shared__ char smraw[];
    uint32_t sbase = s2u(smraw);
    int t = threadIdx.x, lane = t & 31, wid = t >> 5;
    int wm = wid & 1, wn = wid >> 1;
    int m0 = blockIdx.y * 128, n0 = blockIdx.x * 128;
    int z = blockIdx.z, nz = gridDim.z;
    int kslice = K / nz, kbase = z * kslice;
    int npair = kslice / 32;      // all K slices divisible by 32

    const bf* src[4] = {A0 + (size_t)m0*K, A1 + (size_t)m0*K,
                        B0 + (size_t)n0*K, B1 + (size_t)n0*K};

    float acc[4][4][4];
#pragma unroll
    for (int i = 0; i < 4; i++)
#pragma unroll
        for (int j = 0; j < 4; j++)
#pragma unroll
            for (int k = 0; k < 4; k++) acc[i][j][k] = 0.f;

    auto loadStage = [&](int stage, int ko){
        uint32_t stb = sbase + stage*HBUF;
#pragma unroll
        for (int i = 0; i < 4; i++){
            int v = t + i*256;
            int tile = v >> 8, idx = v & 255;
            int row = idx >> 1, grp = idx & 1;
            cpa16(stb + tile*TILEB + row*TP + grp*16,
                  src[tile] + (size_t)row*K + ko + grp*8);
        }
        asm volatile("cp.async.commit_group;":::"memory");
    };

    uint32_t lsel = (lane & 15)*TP + (lane >> 4)*16;
    auto compute = [&](int stage){
        uint32_t stb = sbase + stage*HBUF;
        uint32_t b0[4][2], b1[4][2];
#pragma unroll
        for (int s = 0; s < 2; s++){
#pragma unroll
            for (int jj = 0; jj < 2; jj++){
                uint32_t r[4];
                ldsm4(r, stb + (2+s)*TILEB + (wn*32 + jj*16)*TP + lsel);
                if (s == 0){
                    b0[jj*2  ][0] = r[0]; b0[jj*2  ][1] = r[2];
                    b0[jj*2+1][0] = r[1]; b0[jj*2+1][1] = r[3];
                } else {
                    b1[jj*2  ][0] = r[0]; b1[jj*2  ][1] = r[2];
                    b1[jj*2+1][0] = r[1]; b1[jj*2+1][1] = r[3];
                }
            }
        }
#pragma unroll
        for (int i = 0; i < 4; i++){
            uint32_t a0[4], a1[4];
            ldsm4(a0, stb + 0*TILEB + (wm*64 + i*16)*TP + lsel);
            ldsm4(a1, stb + 1*TILEB + (wm*64 + i*16)*TP + lsel);
#pragma unroll
            for (int j = 0; j < 4; j++){
                mma16816(acc[i][j], a0, b0[j]);
                mma16816(acc[i][j], a0, b1[j]);
                mma16816(acc[i][j], a1, b0[j]);
            }
        }
    };

    loadStage(0, kbase);
    loadStage(1, kbase + 16);

    for (int p = 0; p < npair; p++){
        int c0 = 2*p;
        if (p + 1 < npair){
            loadStage((c0+2)&3, kbase + (c0+2)*16);
            loadStage((c0+3)&3, kbase + (c0+3)*16);
            asm volatile("cp.async.wait_group 2;":::"memory");
        } else {
            asm volatile("cp.async.wait_group 0;":::"memory");
        }
        __syncthreads();
        compute(c0 & 3);
        compute((c0+1) & 3);
        __syncthreads();
    }

    if (mode == 0){
        float* outp = Cp + (size_t)z * MPAD * HID;
#pragma unroll
        for (int i = 0; i < 4; i++){
            int mr = m0 + wm*64 + i*16 + (lane >> 2);
#pragma unroll
            for (int j = 0; j < 4; j++){
                int nc = n0 + wn*32 + j*8 + (lane & 3)*2;
                *(float2*)(outp + (size_t)mr*HID + nc) = make_float2(acc[i][j][0], acc[i][j][1]);
                *(float2*)(outp + (size_t)(mr+8)*HID + nc) = make_float2(acc[i][j][2], acc[i][j][3]);
            }
        }
    } else {
#pragma unroll
        for (int i = 0; i < 4; i++){
#pragma unroll
            for (int j = 0; j < 4; j++){
                int nc = n0 + wn*32 + j*8 + (lane & 3)*2;
#pragma unroll
                for (int h = 0; h < 2; h++){
                    int m = m0 + wm*64 + i*16 + (lane >> 2) + h*8;
                    if (m < NPROP){
                        if (nc < 105)   Oh[(size_t)m*105 + nc]   = acc[i][j][h*2]   + bias[nc];
                        if (nc+1 < 105) Oh[(size_t)m*105 + nc+1] = acc[i][j][h*2+1] + bias[nc+1];
                    }
                }
            }
        }
    }
}

// ---------------- sum 4 split-K partials + bias + relu + split2 ----------------
__global__ void fixup_split(const float* __restrict__ p, const float* __restrict__ bias,
                            bf* __restrict__ o0, bf* __restrict__ o1){
    int i = blockIdx.x*256 + threadIdx.x;
    const int N = MPAD*HID;
    float v = fmaxf(p[i] + p[N + i] + p[2*N + i] + p[3*N + i] + bias[i & (HID-1)], 0.f);
    bf h0, h1; split2(v, h0, h1);
    o0[i] = h0; o1[i] = h1;
}

// ---------------- softmax + decode -> class-major candidates ----------------
__global__ void postproc_kernel(const float* __restrict__ rois){
    int m = blockIdx.x*128 + threadIdx.x;
    if (m >= NPROP) return;
    const float* h = g_head + (size_t)m*105;
    float lg[21], mx = -INFINITY;
#pragma unroll
    for (int c = 0; c < 21; c++){ lg[c] = h[c]; mx = fmaxf(mx, lg[c]); }
    float sum = 0.f;
#pragma unroll
    for (int c = 0; c < 21; c++){ lg[c] = expf(lg[c] - mx); sum += lg[c]; }
    float inv = 1.0f / sum;
    float4 r = ((const float4*)rois)[m];
    float w = r.z - r.x, hh = r.w - r.y;
    float cx = r.x + 0.5f*w, cy = r.y + 0.5f*hh;
#pragma unroll
    for (int c = 1; c < 21; c++){
        float sc = lg[c]*inv;
        float dx = h[21 + c*4 + 0], dy = h[21 + c*4 + 1];
        float dw = h[21 + c*4 + 2], dh = h[21 + c*4 + 3];
        float pcx = dx*w + cx, pcy = dy*hh + cy;
        float pw = expf(dw)*w, ph2 = expf(dh)*hh;
        float x1 = pcx - 0.5f*pw, y1 = pcy - 0.5f*ph2;
        float x2 = pcx + 0.5f*pw, y2 = pcy + 0.5f*ph2;
        int i = (c-1)*1000 + m;
        g_boxesC[i] = make_float4(x1, y1, x2, y2);
        float off = (float)c * 10000.0f;
        g_boxoffC[i] = make_float4(x1 + off, y1 + off, x2 + off, y2 + off);
        g_candC[i] = (sc > 0.05f) ? sc : -1.0f;
    }
}

// ---------------- warp-per-class NMS (no block barriers) ----------------
// lane owns candidates i = j*32+lane (j<32). Tie-break = smallest flat index.
__global__ void class_nms(){
    int cz = blockIdx.x, lane = threadIdx.x;
    __shared__ float4 bx[1000];
    float sc[32];
#pragma unroll
    for (int j = 0; j < 32; j++){
        int i = j*32 + lane;
        sc[j] = (i < 1000) ? g_candC[cz*1000 + i] : -INFINITY;
    }
    for (int i = lane; i < 1000; i += 32)
        bx[i] = g_boxoffC[cz*1000 + i];
    __syncwarp();
    int nk = 0;
    for (int it = 0; it < MAXDET; it++){
        float bv = -INFINITY; int bj = 0;
#pragma unroll
        for (int j = 0; j < 32; j++)
            if (sc[j] > bv){ bv = sc[j]; bj = j; }     // strict > keeps smallest j
        int bi = bj*32 + lane;
#pragma unroll
        for (int o = 16; o; o >>= 1){
            float ov = __shfl_down_sync(~0u, bv, o);
            int oi = __shfl_down_sync(~0u, bi, o);
            if (ov > bv || (ov == bv && oi < bi)){ bv = ov; bi = oi; }
        }
        bv = __shfl_sync(~0u, bv, 0);
        bi = __shfl_sync(~0u, bi, 0);
        if (bv <= 0.05f) break;
        if (lane == 0){
            g_svS[cz*MAXDET + nk] = bv;
            g_svOrd[cz*MAXDET + nk] = bi*20 + cz;
            g_svBox[cz*MAXDET + nk] = g_boxesC[cz*1000 + bi];
        }
        nk++;
        float4 p = bx[bi];
        float pa = (p.z - p.x) * (p.w - p.y);
#pragma unroll
        for (int j = 0; j < 32; j++){
            if (sc[j] > -INFINITY){
                int i = j*32 + lane;
                float4 b = bx[i];
                float ix1 = fmaxf(p.x, b.x), iy1 = fmaxf(p.y, b.y);
                float ix2 = fminf(p.z, b.z), iy2 = fminf(p.w, b.w);
                float inter = fmaxf(ix2 - ix1, 0.f) * fmaxf(iy2 - iy1, 0.f);
                float A = (b.z - b.x) * (b.w - b.y);
                if (inter / (pa + A - inter + 1e-9f) > 0.5f) sc[j] = -INFINITY;
            }
        }
        __syncwarp();
    }
    if (lane == 0) g_svCnt[cz] = nk;
}

// ---------------- 20-way sorted merge -> top-100 (1 warp) ----------------
__global__ void merge_top(float* __restrict__ out){
    int lane = threadIdx.x;
    int head = 0;
    int cnt = (lane < 20) ? g_svCnt[lane] : 0;
    for (int it = 0; it < MAXDET; it++){
        float v; int ord;
        if (lane < 20 && head < cnt){
            v = g_svS[lane*MAXDET + head];
            ord = g_svOrd[lane*MAXDET + head];
        } else { v = -INFINITY; ord = 0x7fffffff; }
        float bv = v; int bord = ord, bl = lane;
#pragma unroll
        for (int o = 16; o; o >>= 1){
            float ov = __shfl_down_sync(~0u, bv, o);
            int oo = __shfl_down_sync(~0u, bord, o);
            int ol = __shfl_down_sync(~0u, bl, o);
            if (ov > bv || (ov == bv && oo < bord)){ bv = ov; bord = oo; bl = ol; }
        }
        bl = __shfl_sync(~0u, bl, 0);
        bv = __shfl_sync(~0u, bv, 0);
        if (bv <= -INFINITY) break;
        if (lane == bl){
            float4 b = g_svBox[lane*MAXDET + head];
            out[it*4+0] = b.x; out[it*4+1] = b.y; out[it*4+2] = b.z; out[it*4+3] = b.w;
            out[400 + it] = bv;
            out[500 + it] = (float)(lane + 1);
            head++;
        }
        __syncwarp();
    }
}

__global__ void zero_out(float* out, int n){
    int i = blockIdx.x*256 + threadIdx.x;
    if (i < n) out[i] = 0.f;
}

// ---------------- launcher ----------------
extern "C" void kernel_launch(void* const* d_in, const int* in_sizes, int n_in,
                              void* d_out, int out_size){
    const float* fm = (const float*)d_in[0];
    const float* pr = (const float*)d_in[1];
    const float* w1 = (const float*)d_in[2];
    const float* b1 = (const float*)d_in[3];
    const float* w2 = (const float*)d_in[4];
    const float* b2 = (const float*)d_in[5];
    const float* wc = (const float*)d_in[6];
    const float* bc = (const float*)d_in[7];
    const float* wb = (const float*)d_in[8];
    const float* bb = (const float*)d_in[9];
    float* out = (float*)d_out;

    bf *A0,*A1,*W10,*W11,*X1a,*X1b,*W20,*W21,*X2a,*X2b,*WH0,*WH1;
    float *bh, *head, *part;
    cudaGetSymbolAddress((void**)&A0, g_A0);   cudaGetSymbolAddress((void**)&A1, g_A1);
    cudaGetSymbolAddress((void**)&W10, g_W10); cudaGetSymbolAddress((void**)&W11, g_W11);
    cudaGetSymbolAddress((void**)&X1a, g_X1a); cudaGetSymbolAddress((void**)&X1b, g_X1b);
    cudaGetSymbolAddress((void**)&W20, g_W20); cudaGetSymbolAddress((void**)&W21, g_W21);
    cudaGetSymbolAddress((void**)&X2a, g_X2a); cudaGetSymbolAddress((void**)&X2b, g_X2b);
    cudaGetSymbolAddress((void**)&WH0, g_WH0); cudaGetSymbolAddress((void**)&WH1, g_WH1);
    cudaGetSymbolAddress((void**)&bh, g_bh);   cudaGetSymbolAddress((void**)&head, g_head);
    cudaGetSymbolAddress((void**)&part, g_part);

    cudaFuncSetAttribute(gemm_mma, cudaFuncAttributeMaxDynamicSharedMemorySize, GSMEM);

    conv_T_perm<<<dim3(392, 32), dim3(32, 8)>>>(w1, W10, W11);        // 1
    transpose_fm<<<dim3(313, 8), dim3(32, 8)>>>(fm);                  // 2
    roi_align_kernel<<<NPROP, 256>>>(pr);                             // 3
    gemm_mma<<<dim3(8, 8, 4), 256, GSMEM>>>(A0, A1, W10, W11,         // 4 (profiled)
                                            nullptr, K1, 0, part, nullptr);
    fixup_split<<<MPAD*HID/256, 256>>>(part, b1, X1a, X1b);           // 5
    conv_T<<<dim3(32, 32), dim3(32, 8)>>>(w2, HID, HID, W20, W21);    // 6
    gemm_mma<<<dim3(8, 8, 4), 256, GSMEM>>>(X1a, X1b, W20, W21,       // 7
                                            nullptr, HID, 0, part, nullptr);
    fixup_split<<<MPAD*HID/256, 256>>>(part, b2, X2a, X2b);           // 8
    conv_heads<<<128, 256>>>(wc, bc, wb, bb);                         // 9
    gemm_mma<<<dim3(1, 8, 1), 256, GSMEM>>>(X2a, X2b, WH0, WH1,       // 10
                                            bh, HID, 1, nullptr, head);
    zero_out<<<(out_size + 255) / 256, 256>>>(out, out_size);         // 11
    postproc_kernel<<<8, 128>>>(pr);                                  // 12
    class_nms<<<20, 32>>>();                                          // 13
    merge_top<<<1, 32>>>(out);                                        // 14
}

// round 13
// speedup vs baseline: 1.7979x; 1.7979x over previous
#include <cuda_runtime.h>
#include <cuda_bf16.h>
#include <math.h>
#include <stdint.h>

#define NPROP 1000
#define MPAD  1024
#define FM_HW 10000
#define K1    12544
#define HID   1024
#define MAXDET 100

typedef __nv_bfloat16 bf;
typedef unsigned long long ull;

// ---------------- scratch ----------------
__device__ float g_fmT[FM_HW * 256];
__device__ bf g_A0[MPAD*K1], g_A1[MPAD*K1];
__device__ bf g_W10[HID*K1], g_W11[HID*K1];
__device__ bf g_X1a[MPAD*HID], g_X1b[MPAD*HID];
__device__ bf g_W20[HID*HID], g_W21[HID*HID];
__device__ bf g_X2a[MPAD*HID], g_X2b[MPAD*HID];
__device__ bf g_WH0[128*HID], g_WH1[128*HID];
__device__ float g_bh[128];
__device__ float g_part[4 * MPAD * HID];
__device__ float g_head[NPROP * 105];
__device__ float  g_candC[20*1000];
__device__ float4 g_boxesC[20*1000], g_boxoffC[20*1000];
__device__ float  g_svS[20*MAXDET];
__device__ int    g_svOrd[20*MAXDET];
__device__ float4 g_svBox[20*MAXDET];
__device__ int    g_svCnt[20];

// ---------------- PTX helpers ----------------
__device__ __forceinline__ uint32_t s2u(const void* p){
    uint32_t a; asm("{ .reg .u64 t; cvta.to.shared.u64 t, %1; cvt.u32.u64 %0, t; }":"=r"(a):"l"(p)); return a;
}
__device__ __forceinline__ void cpa16(uint32_t s, const void* g){
    asm volatile("cp.async.cg.shared.global [%0], [%1], 16;"::"r"(s),"l"(g):"memory");
}
__device__ __forceinline__ void ldsm4(uint32_t* r, uint32_t addr){
    asm volatile("ldmatrix.sync.aligned.m8n8.x4.shared.b16 {%0,%1,%2,%3}, [%4];"
        :"=r"(r[0]),"=r"(r[1]),"=r"(r[2]),"=r"(r[3]):"r"(addr));
}
__device__ __forceinline__ void mma16816(float* d, const uint32_t* a, const uint32_t* b){
    asm volatile("mma.sync.aligned.m16n8k16.row.col.f32.bf16.bf16.f32 "
        "{%0,%1,%2,%3}, {%4,%5,%6,%7}, {%8,%9}, {%0,%1,%2,%3};"
        :"+f"(d[0]),"+f"(d[1]),"+f"(d[2]),"+f"(d[3])
        :"r"(a[0]),"r"(a[1]),"r"(a[2]),"r"(a[3]),"r"(b[0]),"r"(b[1]));
}
__device__ __forceinline__ void split2(float v, bf& b0, bf& b1){
    b0 = __float2bfloat16(v);
    b1 = __float2bfloat16(v - __bfloat162float(b0));
}

// ---------------- w1 transpose + permute + split ----------------
__global__ void conv_T_perm(const float* __restrict__ in,
                            bf* __restrict__ o0, bf* __restrict__ o1){
    __shared__ float tl[32][33];
    int bx = blockIdx.x;
    int cell = bx >> 3, c0 = (bx & 7) * 32;
    int h0 = blockIdx.y * 32;
    int tx = threadIdx.x, ty = threadIdx.y;
#pragma unroll
    for (int j = 0; j < 32; j += 8){
        int c = c0 + ty + j;
        int r = c * 49 + cell;
        tl[ty+j][tx] = in[(size_t)r * HID + h0 + tx];
    }
    __syncthreads();
#pragma unroll
    for (int j = 0; j < 32; j += 8){
        int h = h0 + ty + j;
        float v = tl[tx][ty+j];
        size_t o = (size_t)h * K1 + cell*256 + c0 + tx;
        bf h0b, h1b; split2(v, h0b, h1b);
        o0[o] = h0b; o1[o] = h1b;
    }
}

// ---------------- plain transpose + split ----------------
__global__ void conv_T(const float* __restrict__ in, int R, int C,
                       bf* __restrict__ o0, bf* __restrict__ o1){
    __shared__ float tl[32][33];
    int r0 = blockIdx.y*32, c0 = blockIdx.x*32, tx = threadIdx.x, ty = threadIdx.y;
#pragma unroll
    for (int j = 0; j < 32; j += 8)
        tl[ty+j][tx] = in[(size_t)(r0+ty+j)*C + c0 + tx];
    __syncthreads();
#pragma unroll
    for (int j = 0; j < 32; j += 8){
        float v = tl[tx][ty+j];
        size_t o = (size_t)(c0+ty+j)*R + r0 + tx;
        bf h0, h1; split2(v, h0, h1);
        o0[o] = h0; o1[o] = h1;
    }
}

// ---------------- transpose FM ----------------
__global__ void transpose_fm(const float* __restrict__ fm){
    __shared__ float tl[32][33];
    int hw0 = blockIdx.x*32, c0 = blockIdx.y*32, tx = threadIdx.x, ty = threadIdx.y;
#pragma unroll
    for (int j = 0; j < 32; j += 8){
        int hw = hw0 + tx;
        tl[ty+j][tx] = (hw < FM_HW) ? fm[(c0+ty+j)*FM_HW + hw] : 0.f;
    }
    __syncthreads();
#pragma unroll
    for (int j = 0; j < 32; j += 8){
        int hw = hw0 + ty + j;
        if (hw < FM_HW) g_fmT[hw*256 + c0 + tx] = tl[tx][ty+j];
    }
}

// ---------------- ROI align -> split-bf16 A ----------------
__global__ void roi_align_kernel(const float* __restrict__ rois){
    int n = blockIdx.x, t = threadIdx.x;
    int tc = t & 63, cg = t >> 6;
    float4 r = ((const float4*)rois)[n];
    float b0 = r.x*0.125f - 0.5f, b1 = r.y*0.125f - 0.5f;
    float bw = (r.z*0.125f - 0.5f - b0) / 7.0f, bh = (r.w*0.125f - 0.5f - b1) / 7.0f;
    __shared__ int sx0[14], sx1[14], sy0[14], sy1[14];
    __shared__ float swx0[14], swx1[14], swy0[14], swy1[14], svx[14], svy[14];
    if (t < 14){
        int p = t >> 1, s = t & 1;
        float off = (float)p + ((float)s + 0.5f)*0.5f;
        float v = b0 + off*bw;
        svx[t] = (v >= -1.f && v <= 100.f) ? 1.f : 0.f;
        v = fminf(fmaxf(v, 0.f), 99.f);
        float v0 = floorf(v); int i0 = (int)v0;
        sx0[t] = i0; sx1[t] = min(i0+1, 99); swx1[t] = v - v0; swx0[t] = 1.f - (v - v0);
        v = b1 + off*bh;
        svy[t] = (v >= -1.f && v <= 100.f) ? 1.f : 0.f;
        v = fminf(fmaxf(v, 0.f), 99.f);
        v0 = floorf(v); i0 = (int)v0;
        sy0[t] = i0; sy1[t] = min(i0+1, 99); swy1[t] = v - v0; swy0[t] = 1.f - (v - v0);
    }
    __syncthreads();
    const float4* fmT4 = (const float4*)g_fmT;
    bf* a0p = g_A0 + (size_t)n*K1;
    bf* a1p = g_A1 + (size_t)n*K1;
    for (int cell = cg; cell < 49; cell += 4){
        int ph = cell / 7, pw = cell - ph*7;
        float ax = 0, ay = 0, az = 0, aw = 0;
#pragma unroll
        for (int sy = 0; sy < 2; sy++){
            int j = ph*2 + sy;
            int y0 = sy0[j], y1 = sy1[j];
            float wy0 = swy0[j], wy1 = swy1[j], vy = svy[j];
#pragma unroll
            for (int sx = 0; sx < 2; sx++){
                int k = pw*2 + sx;
                if (vy * svx[k] != 0.f){
                    int x0 = sx0[k], x1 = sx1[k];
                    float w00 = wy0*swx0[k], w01 = wy0*swx1[k], w10 = wy1*swx0[k], w11 = wy1*swx1[k];
                    float4 f00 = fmT4[(y0*100+x0)*64+tc], f01 = fmT4[(y0*100+x1)*64+tc];
                    float4 f10 = fmT4[(y1*100+x0)*64+tc], f11 = fmT4[(y1*100+x1)*64+tc];
                    ax += w00*f00.x + w01*f01.x + w10*f10.x + w11*f11.x;
                    ay += w00*f00.y + w01*f01.y + w10*f10.y + w11*f11.y;
                    az += w00*f00.z + w01*f01.z + w10*f10.z + w11*f11.z;
                    aw += w00*f00.w + w01*f01.w + w10*f10.w + w11*f11.w;
                }
            }
        }
        float vals[4] = {ax*0.25f, ay*0.25f, az*0.25f, aw*0.25f};
        bf p0[4], p1[4];
#pragma unroll
        for (int i = 0; i < 4; i++) split2(vals[i], p0[i], p1[i]);
        int base = cell*256 + tc*4;
        *(ull*)(a0p + base) = *(ull*)p0;
        *(ull*)(a1p + base) = *(ull*)p1;
    }
}

// ---------------- heads weights ----------------
__global__ void conv_heads(const float* __restrict__ wc, const float* __restrict__ bc,
                           const float* __restrict__ wb, const float* __restrict__ bb){
    int h = blockIdx.x;
    for (int k = threadIdx.x; k < HID; k += 256){
        float v = (h < 21) ? wc[k*21 + h] : ((h < 105) ? wb[k*84 + (h-21)] : 0.f);
        bf h0, h1; split2(v, h0, h1);
        size_t o = (size_t)h*HID + k;
        g_WH0[o] = h0; g_WH1[o] = h1;
    }
    if (threadIdx.x == 0)
        g_bh[h] = (h < 21) ? bc[h] : ((h < 105) ? bb[h-21] : 0.f);
}

// ---------------- mma.sync bf16 GEMM (split-2, 3 terms), 512 thr 4x4 warps -----
#define TP    48
#define TILEB (128*TP)           // 6144
#define BUFB  (4*TILEB)          // 24576
#define GSMEM (2*BUFB)           // 49152

__global__ __launch_bounds__(512, 2)
void gemm_mma(const bf* __restrict__ A0, const bf* __restrict__ A1,
              const bf* __restrict__ B0, const bf* __restrict__ B1,
              const float* __restrict__ bias, int K, int mode,
              float* __restrict__ Cp, float* __restrict__ Oh){
    extern __shared__ char smraw[];
    uint32_t sbase = s2u(smraw);
    int t = threadIdx.x, lane = t & 31, wid = t >> 5;
    int wm = wid & 3, wn = wid >> 2;          // 4 x 4 warps, each 32m x 32n
    int m0 = blockIdx.y * 128, n0 = blockIdx.x * 128;
    int z = blockIdx.z, nz = gridDim.z;
    int kslice = K / nz, kbase = z * kslice, nch = kslice / 16;

    const bf* src[4] = {A0 + (size_t)m0*K, A1 + (size_t)m0*K,
                        B0 + (size_t)n0*K, B1 + (size_t)n0*K};

    float acc[2][4][4];
#pragma unroll
    for (int i = 0; i < 2; i++)
#pragma unroll
        for (int j = 0; j < 4; j++)
#pragma unroll
            for (int k = 0; k < 4; k++) acc[i][j][k] = 0.f;

    auto loadChunk = [&](uint32_t stb, int ko){
#pragma unroll
        for (int i = 0; i < 2; i++){
            int v = t + i*512;
            int tile = v >> 8, idx = v & 255;
            int row = idx >> 1, grp = idx & 1;
            cpa16(stb + tile*TILEB + row*TP + grp*16,
                  src[tile] + (size_t)row*K + ko + grp*8);
        }
        asm volatile("cp.async.commit_group;":::"memory");
    };

    loadChunk(sbase, kbase);

    uint32_t lsel = (lane & 15)*TP + (lane >> 4)*16;
    for (int c = 0; c < nch; c++){
        int buf = c & 1;
        if (c + 1 < nch){
            loadChunk(sbase + (buf^1)*BUFB, kbase + (c+1)*16);
            asm volatile("cp.async.wait_group 1;":::"memory");
        } else {
            asm volatile("cp.async.wait_group 0;":::"memory");
        }
        __syncthreads();
        uint32_t stb = sbase + buf*BUFB;
        // B fragments: 32 cols (wn*32 + jj*16), both splits
        uint32_t b0[4][2], b1[4][2];
#pragma unroll
        for (int s = 0; s < 2; s++){
#pragma unroll
            for (int jj = 0; jj < 2; jj++){
                uint32_t r[4];
                ldsm4(r, stb + (2+s)*TILEB + (wn*32 + jj*16)*TP + lsel);
                if (s == 0){
                    b0[jj*2  ][0] = r[0]; b0[jj*2  ][1] = r[2];
                    b0[jj*2+1][0] = r[1]; b0[jj*2+1][1] = r[3];
                } else {
                    b1[jj*2  ][0] = r[0]; b1[jj*2  ][1] = r[2];
                    b1[jj*2+1][0] = r[1]; b1[jj*2+1][1] = r[3];
                }
            }
        }
#pragma unroll
        for (int i = 0; i < 2; i++){
            uint32_t a0[4], a1[4];
            ldsm4(a0, stb + 0*TILEB + (wm*32 + i*16)*TP + lsel);
            ldsm4(a1, stb + 1*TILEB + (wm*32 + i*16)*TP + lsel);
#pragma unroll
            for (int j = 0; j < 4; j++){
                mma16816(acc[i][j], a0, b0[j]);
                mma16816(acc[i][j], a0, b1[j]);
                mma16816(acc[i][j], a1, b0[j]);
            }
        }
        __syncthreads();
    }

    if (mode == 0){
        float* outp = Cp + (size_t)z * MPAD * HID;
#pragma unroll
        for (int i = 0; i < 2; i++){
            int mr = m0 + wm*32 + i*16 + (lane >> 2);
#pragma unroll
            for (int j = 0; j < 4; j++){
                int nc = n0 + wn*32 + j*8 + (lane & 3)*2;
                *(float2*)(outp + (size_t)mr*HID + nc) = make_float2(acc[i][j][0], acc[i][j][1]);
                *(float2*)(outp + (size_t)(mr+8)*HID + nc) = make_float2(acc[i][j][2], acc[i][j][3]);
            }
        }
    } else {
#pragma unroll
        for (int i = 0; i < 2; i++){
#pragma unroll
            for (int j = 0; j < 4; j++){
                int nc = n0 + wn*32 + j*8 + (lane & 3)*2;
#pragma unroll
                for (int h = 0; h < 2; h++){
                    int m = m0 + wm*32 + i*16 + (lane >> 2) + h*8;
                    if (m < NPROP){
                        if (nc < 105)   Oh[(size_t)m*105 + nc]   = acc[i][j][h*2]   + bias[nc];
                        if (nc+1 < 105) Oh[(size_t)m*105 + nc+1] = acc[i][j][h*2+1] + bias[nc+1];
                    }
                }
            }
        }
    }
}

// ---------------- sum 4 split-K partials + bias + relu + split2 ----------------
__global__ void fixup_split(const float* __restrict__ p, const float* __restrict__ bias,
                            bf* __restrict__ o0, bf* __restrict__ o1){
    int i = blockIdx.x*256 + threadIdx.x;
    const int N = MPAD*HID;
    float v = fmaxf(p[i] + p[N + i] + p[2*N + i] + p[3*N + i] + bias[i & (HID-1)], 0.f);
    bf h0, h1; split2(v, h0, h1);
    o0[i] = h0; o1[i] = h1;
}

// ---------------- softmax + decode -> class-major candidates ----------------
__global__ void postproc_kernel(const float* __restrict__ rois){
    int m = blockIdx.x*128 + threadIdx.x;
    if (m >= NPROP) return;
    const float* h = g_head + (size_t)m*105;
    float lg[21], mx = -INFINITY;
#pragma unroll
    for (int c = 0; c < 21; c++){ lg[c] = h[c]; mx = fmaxf(mx, lg[c]); }
    float sum = 0.f;
#pragma unroll
    for (int c = 0; c < 21; c++){ lg[c] = expf(lg[c] - mx); sum += lg[c]; }
    float inv = 1.0f / sum;
    float4 r = ((const float4*)rois)[m];
    float w = r.z - r.x, hh = r.w - r.y;
    float cx = r.x + 0.5f*w, cy = r.y + 0.5f*hh;
#pragma unroll
    for (int c = 1; c < 21; c++){
        float sc = lg[c]*inv;
        float dx = h[21 + c*4 + 0], dy = h[21 + c*4 + 1];
        float dw = h[21 + c*4 + 2], dh = h[21 + c*4 + 3];
        float pcx = dx*w + cx, pcy = dy*hh + cy;
        float pw = expf(dw)*w, ph2 = expf(dh)*hh;
        float x1 = pcx - 0.5f*pw, y1 = pcy - 0.5f*ph2;
        float x2 = pcx + 0.5f*pw, y2 = pcy + 0.5f*ph2;
        int i = (c-1)*1000 + m;
        g_boxesC[i] = make_float4(x1, y1, x2, y2);
        float off = (float)c * 10000.0f;
        g_boxoffC[i] = make_float4(x1 + off, y1 + off, x2 + off, y2 + off);
        g_candC[i] = (sc > 0.05f) ? sc : -1.0f;
    }
}

// ---------------- per-class greedy NMS, capped at MAXDET picks ----------------
__global__ void class_nms(){
    int cz = blockIdx.x, t = threadIdx.x;
    __shared__ float sc[1000];
    __shared__ float4 bx[1000];
    __shared__ float rv[8]; __shared__ int ri[8];
    __shared__ float4 pbS; __shared__ int s_stop, s_nk;
    for (int i = t; i < 1000; i += 256){
        sc[i] = g_candC[cz*1000 + i];
        bx[i] = g_boxoffC[cz*1000 + i];
    }
    if (t == 0){ s_stop = 0; s_nk = 0; }
    __syncthreads();
    for (int it = 0; it < MAXDET; it++){
        float bv = -INFINITY; int bi = 1 << 30;
#pragma unroll
        for (int w = 0; w < 4; w++){
            int i = t + (w << 8);
            if (i < 1000){
                float v = sc[i];
                if (v > bv || (v == bv && i < bi)){ bv = v; bi = i; }
            }
        }
#pragma unroll
        for (int o = 16; o; o >>= 1){
            float ov = __shfl_down_sync(~0u, bv, o);
            int oi = __shfl_down_sync(~0u, bi, o);
            if (ov > bv || (ov == bv && oi < bi)){ bv = ov; bi = oi; }
        }
        if ((t & 31) == 0){ rv[t >> 5] = bv; ri[t >> 5] = bi; }
        __syncthreads();
        if (t == 0){
            float mb = -INFINITY; int mi = 1 << 30;
#pragma unroll
            for (int k = 0; k < 8; k++)
                if (rv[k] > mb || (rv[k] == mb && ri[k] < mi)){ mb = rv[k]; mi = ri[k]; }
            if (mb > 0.05f){
                int slot = s_nk++;
                g_svS[cz*MAXDET + slot] = mb;
                g_svOrd[cz*MAXDET + slot] = mi*20 + cz;
                g_svBox[cz*MAXDET + slot] = g_boxesC[cz*1000 + mi];
                pbS = bx[mi];
            } else s_stop = 1;
        }
        __syncthreads();
        if (s_stop) break;
        float4 p = pbS;
        float pa = (p.z - p.x) * (p.w - p.y);
#pragma unroll
        for (int w = 0; w < 4; w++){
            int i = t + (w << 8);
            if (i < 1000){
                float v = sc[i];
                if (v > -INFINITY){
                    float4 b = bx[i];
                    float ix1 = fmaxf(p.x, b.x), iy1 = fmaxf(p.y, b.y);
                    float ix2 = fminf(p.z, b.z), iy2 = fminf(p.w, b.w);
                    float inter = fmaxf(ix2 - ix1, 0.f) * fmaxf(iy2 - iy1, 0.f);
                    float A = (b.z - b.x) * (b.w - b.y);
                    if (inter / (pa + A - inter + 1e-9f) > 0.5f) sc[i] = -INFINITY;
                }
            }
        }
        __syncthreads();
    }
    if (t == 0) g_svCnt[cz] = s_nk;
}

// ---------------- 20-way sorted merge -> top-100 (1 warp) ----------------
__global__ void merge_top(float* __restrict__ out){
    int lane = threadIdx.x;
    int head = 0;
    int cnt = (lane < 20) ? g_svCnt[lane] : 0;
    for (int it = 0; it < MAXDET; it++){
        float v; int ord;
        if (lane < 20 && head < cnt){
            v = g_svS[lane*MAXDET + head];
            ord = g_svOrd[lane*MAXDET + head];
        } else { v = -INFINITY; ord = 0x7fffffff; }
        float bv = v; int bord = ord, bl = lane;
#pragma unroll
        for (int o = 16; o; o >>= 1){
            float ov = __shfl_down_sync(~0u, bv, o);
            int oo = __shfl_down_sync(~0u, bord, o);
            int ol = __shfl_down_sync(~0u, bl, o);
            if (ov > bv || (ov == bv && oo < bord)){ bv = ov; bord = oo; bl = ol; }
        }
        bl = __shfl_sync(~0u, bl, 0);
        bv = __shfl_sync(~0u, bv, 0);
        if (bv <= -INFINITY) break;
        if (lane == bl){
            float4 b = g_svBox[lane*MAXDET + head];
            out[it*4+0] = b.x; out[it*4+1] = b.y; out[it*4+2] = b.z; out[it*4+3] = b.w;
            out[400 + it] = bv;
            out[500 + it] = (float)(lane + 1);
            head++;
        }
        __syncwarp();
    }
}

__global__ void zero_out(float* out, int n){
    int i = blockIdx.x*256 + threadIdx.x;
    if (i < n) out[i] = 0.f;
}

// ---------------- launcher ----------------
extern "C" void kernel_launch(void* const* d_in, const int* in_sizes, int n_in,
                              void* d_out, int out_size){
    const float* fm = (const float*)d_in[0];
    const float* pr = (const float*)d_in[1];
    const float* w1 = (const float*)d_in[2];
    const float* b1 = (const float*)d_in[3];
    const float* w2 = (const float*)d_in[4];
    const float* b2 = (const float*)d_in[5];
    const float* wc = (const float*)d_in[6];
    const float* bc = (const float*)d_in[7];
    const float* wb = (const float*)d_in[8];
    const float* bb = (const float*)d_in[9];
    float* out = (float*)d_out;

    bf *A0,*A1,*W10,*W11,*X1a,*X1b,*W20,*W21,*X2a,*X2b,*WH0,*WH1;
    float *bh, *head, *part;
    cudaGetSymbolAddress((void**)&A0, g_A0);   cudaGetSymbolAddress((void**)&A1, g_A1);
    cudaGetSymbolAddress((void**)&W10, g_W10); cudaGetSymbolAddress((void**)&W11, g_W11);
    cudaGetSymbolAddress((void**)&X1a, g_X1a); cudaGetSymbolAddress((void**)&X1b, g_X1b);
    cudaGetSymbolAddress((void**)&W20, g_W20); cudaGetSymbolAddress((void**)&W21, g_W21);
    cudaGetSymbolAddress((void**)&X2a, g_X2a); cudaGetSymbolAddress((void**)&X2b, g_X2b);
    cudaGetSymbolAddress((void**)&WH0, g_WH0); cudaGetSymbolAddress((void**)&WH1, g_WH1);
    cudaGetSymbolAddress((void**)&bh, g_bh);   cudaGetSymbolAddress((void**)&head, g_head);
    cudaGetSymbolAddress((void**)&part, g_part);

    cudaFuncSetAttribute(gemm_mma, cudaFuncAttributeMaxDynamicSharedMemorySize, GSMEM);

    conv_T_perm<<<dim3(392, 32), dim3(32, 8)>>>(w1, W10, W11);        // 1
    transpose_fm<<<dim3(313, 8), dim3(32, 8)>>>(fm);                  // 2
    roi_align_kernel<<<NPROP, 256>>>(pr);                             // 3
    gemm_mma<<<dim3(8, 8, 4), 512, GSMEM>>>(A0, A1, W10, W11,         // 4 (profiled)
                                            nullptr, K1, 0, part, nullptr);
    fixup_split<<<MPAD*HID/256, 256>>>(part, b1, X1a, X1b);           // 5
    conv_T<<<dim3(32, 32), dim3(32, 8)>>>(w2, HID, HID, W20, W21);    // 6
    gemm_mma<<<dim3(8, 8, 4), 512, GSMEM>>>(X1a, X1b, W20, W21,       // 7
                                            nullptr, HID, 0, part, nullptr);
    fixup_split<<<MPAD*HID/256, 256>>>(part, b2, X2a, X2b);           // 8
    conv_heads<<<128, 256>>>(wc, bc, wb, bb);                         // 9
    gemm_mma<<<dim3(1, 8, 1), 512, GSMEM>>>(X2a, X2b, WH0, WH1,       // 10
                                            bh, HID, 1, nullptr, head);
    zero_out<<<(out_size + 255) / 256, 256>>>(out, out_size);         // 11
    postproc_kernel<<<8, 128>>>(pr);                                  // 12
    class_nms<<<20, 256>>>();                                         // 13
    merge_top<<<1, 32>>>(out);                                        // 14
}

// round 14
// speedup vs baseline: 1.8562x; 1.0324x over previous
#include <cuda_runtime.h>
#include <cuda_bf16.h>
#include <math.h>
#include <stdint.h>

#define NPROP 1000
#define MPAD  1024
#define FM_HW 10000
#define K1    12544
#define HID   1024
#define MAXDET 100

typedef __nv_bfloat16 bf;
typedef unsigned long long ull;

// ---------------- scratch ----------------
__device__ float g_fmT[FM_HW * 256];
__device__ bf g_A0[MPAD*K1], g_A1[MPAD*K1];
__device__ bf g_W10[HID*K1], g_W11[HID*K1];
__device__ bf g_X1a[MPAD*HID], g_X1b[MPAD*HID];
__device__ bf g_W20[HID*HID], g_W21[HID*HID];
__device__ bf g_X2a[MPAD*HID], g_X2b[MPAD*HID];
__device__ bf g_WH0[128*HID], g_WH1[128*HID];
__device__ float g_bh[128];
__device__ float g_part[4 * MPAD * HID];
__device__ float g_head[NPROP * 105];
__device__ float  g_candC[20*1000];
__device__ float4 g_boxesC[20*1000], g_boxoffC[20*1000];
__device__ float  g_svS[20*MAXDET];
__device__ int    g_svOrd[20*MAXDET];
__device__ float4 g_svBox[20*MAXDET];
__device__ int    g_svCnt[20];

// ---------------- PTX helpers ----------------
__device__ __forceinline__ uint32_t s2u(const void* p){
    uint32_t a; asm("{ .reg .u64 t; cvta.to.shared.u64 t, %1; cvt.u32.u64 %0, t; }":"=r"(a):"l"(p)); return a;
}
__device__ __forceinline__ void cpa16(uint32_t s, const void* g){
    asm volatile("cp.async.cg.shared.global [%0], [%1], 16;"::"r"(s),"l"(g):"memory");
}
__device__ __forceinline__ void ldsm4(uint32_t* r, uint32_t addr){
    asm volatile("ldmatrix.sync.aligned.m8n8.x4.shared.b16 {%0,%1,%2,%3}, [%4];"
        :"=r"(r[0]),"=r"(r[1]),"=r"(r[2]),"=r"(r[3]):"r"(addr));
}
__device__ __forceinline__ void mma16816(float* d, const uint32_t* a, const uint32_t* b){
    asm volatile("mma.sync.aligned.m16n8k16.row.col.f32.bf16.bf16.f32 "
        "{%0,%1,%2,%3}, {%4,%5,%6,%7}, {%8,%9}, {%0,%1,%2,%3};"
        :"+f"(d[0]),"+f"(d[1]),"+f"(d[2]),"+f"(d[3])
        :"r"(a[0]),"r"(a[1]),"r"(a[2]),"r"(a[3]),"r"(b[0]),"r"(b[1]));
}
__device__ __forceinline__ void split2(float v, bf& b0, bf& b1){
    b0 = __float2bfloat16(v);
    b1 = __float2bfloat16(v - __bfloat162float(b0));
}

// ---------------- fused prep: all independent conversions in one launch --------
// blocks [0,12544): conv_T_perm(w1)   [12544,15048): transpose_fm
// [15048,16072): conv_T(w2)           [16072,16200): conv_heads
__global__ void prep_kernel(const float* __restrict__ w1, const float* __restrict__ fm,
                            const float* __restrict__ w2,
                            const float* __restrict__ wc, const float* __restrict__ bc,
                            const float* __restrict__ wb, const float* __restrict__ bb){
    __shared__ float tl[32][33];
    int b = blockIdx.x, t = threadIdx.x;
    int tx = t & 31, ty = t >> 5;
    if (b < 12544){
        int bx = b % 392, by = b / 392;
        int cell = bx >> 3, c0 = (bx & 7) * 32;
        int h0 = by * 32;
#pragma unroll
        for (int j = 0; j < 32; j += 8){
            int c = c0 + ty + j;
            tl[ty+j][tx] = w1[(size_t)(c * 49 + cell) * HID + h0 + tx];
        }
        __syncthreads();
#pragma unroll
        for (int j = 0; j < 32; j += 8){
            int h = h0 + ty + j;
            float v = tl[tx][ty+j];
            size_t o = (size_t)h * K1 + cell*256 + c0 + tx;
            bf h0b, h1b; split2(v, h0b, h1b);
            g_W10[o] = h0b; g_W11[o] = h1b;
        }
    } else if (b < 15048){
        int r = b - 12544;
        int hw0 = (r % 313) * 32, c0 = (r / 313) * 32;
#pragma unroll
        for (int j = 0; j < 32; j += 8){
            int hw = hw0 + tx;
            tl[ty+j][tx] = (hw < FM_HW) ? fm[(c0+ty+j)*FM_HW + hw] : 0.f;
        }
        __syncthreads();
#pragma unroll
        for (int j = 0; j < 32; j += 8){
            int hw = hw0 + ty + j;
            if (hw < FM_HW) g_fmT[hw*256 + c0 + tx] = tl[tx][ty+j];
        }
    } else if (b < 16072){
        int r = b - 15048;
        int c0 = (r & 31) * 32, r0 = (r >> 5) * 32;
#pragma unroll
        for (int j = 0; j < 32; j += 8)
            tl[ty+j][tx] = w2[(size_t)(r0+ty+j)*HID + c0 + tx];
        __syncthreads();
#pragma unroll
        for (int j = 0; j < 32; j += 8){
            float v = tl[tx][ty+j];
            size_t o = (size_t)(c0+ty+j)*HID + r0 + tx;
            bf h0, h1; split2(v, h0, h1);
            g_W20[o] = h0; g_W21[o] = h1;
        }
    } else {
        int h = b - 16072;
        for (int k = t; k < HID; k += 256){
            float v = (h < 21) ? wc[k*21 + h] : ((h < 105) ? wb[k*84 + (h-21)] : 0.f);
            bf h0, h1; split2(v, h0, h1);
            size_t o = (size_t)h*HID + k;
            g_WH0[o] = h0; g_WH1[o] = h1;
        }
        if (t == 0)
            g_bh[h] = (h < 21) ? bc[h] : ((h < 105) ? bb[h-21] : 0.f);
    }
}

// ---------------- ROI align -> split-bf16 A ----------------
__global__ void roi_align_kernel(const float* __restrict__ rois){
    int n = blockIdx.x, t = threadIdx.x;
    int tc = t & 63, cg = t >> 6;
    float4 r = ((const float4*)rois)[n];
    float b0 = r.x*0.125f - 0.5f, b1 = r.y*0.125f - 0.5f;
    float bw = (r.z*0.125f - 0.5f - b0) / 7.0f, bh = (r.w*0.125f - 0.5f - b1) / 7.0f;
    __shared__ int sx0[14], sx1[14], sy0[14], sy1[14];
    __shared__ float swx0[14], swx1[14], swy0[14], swy1[14], svx[14], svy[14];
    if (t < 14){
        int p = t >> 1, s = t & 1;
        float off = (float)p + ((float)s + 0.5f)*0.5f;
        float v = b0 + off*bw;
        svx[t] = (v >= -1.f && v <= 100.f) ? 1.f : 0.f;
        v = fminf(fmaxf(v, 0.f), 99.f);
        float v0 = floorf(v); int i0 = (int)v0;
        sx0[t] = i0; sx1[t] = min(i0+1, 99); swx1[t] = v - v0; swx0[t] = 1.f - (v - v0);
        v = b1 + off*bh;
        svy[t] = (v >= -1.f && v <= 100.f) ? 1.f : 0.f;
        v = fminf(fmaxf(v, 0.f), 99.f);
        v0 = floorf(v); i0 = (int)v0;
        sy0[t] = i0; sy1[t] = min(i0+1, 99); swy1[t] = v - v0; swy0[t] = 1.f - (v - v0);
    }
    __syncthreads();
    const float4* fmT4 = (const float4*)g_fmT;
    bf* a0p = g_A0 + (size_t)n*K1;
    bf* a1p = g_A1 + (size_t)n*K1;
    for (int cell = cg; cell < 49; cell += 4){
        int ph = cell / 7, pw = cell - ph*7;
        float ax = 0, ay = 0, az = 0, aw = 0;
#pragma unroll
        for (int sy = 0; sy < 2; sy++){
            int j = ph*2 + sy;
            int y0 = sy0[j], y1 = sy1[j];
            float wy0 = swy0[j], wy1 = swy1[j], vy = svy[j];
#pragma unroll
            for (int sx = 0; sx < 2; sx++){
                int k = pw*2 + sx;
                if (vy * svx[k] != 0.f){
                    int x0 = sx0[k], x1 = sx1[k];
                    float w00 = wy0*swx0[k], w01 = wy0*swx1[k], w10 = wy1*swx0[k], w11 = wy1*swx1[k];
                    float4 f00 = fmT4[(y0*100+x0)*64+tc], f01 = fmT4[(y0*100+x1)*64+tc];
                    float4 f10 = fmT4[(y1*100+x0)*64+tc], f11 = fmT4[(y1*100+x1)*64+tc];
                    ax += w00*f00.x + w01*f01.x + w10*f10.x + w11*f11.x;
                    ay += w00*f00.y + w01*f01.y + w10*f10.y + w11*f11.y;
                    az += w00*f00.z + w01*f01.z + w10*f10.z + w11*f11.z;
                    aw += w00*f00.w + w01*f01.w + w10*f10.w + w11*f11.w;
                }
            }
        }
        float vals[4] = {ax*0.25f, ay*0.25f, az*0.25f, aw*0.25f};
        bf p0[4], p1[4];
#pragma unroll
        for (int i = 0; i < 4; i++) split2(vals[i], p0[i], p1[i]);
        int base = cell*256 + tc*4;
        *(ull*)(a0p + base) = *(ull*)p0;
        *(ull*)(a1p + base) = *(ull*)p1;
    }
}

// ---------------- mma.sync bf16 GEMM (split-2, 3 terms), R11 config + e-outer --
#define TP    48
#define TILEB (128*TP)           // 6144
#define BUFB  (4*TILEB)          // 24576
#define GSMEM (2*BUFB)           // 49152

__global__ __launch_bounds__(256, 2)
void gemm_mma(const bf* __restrict__ A0, const bf* __restrict__ A1,
              const bf* __restrict__ B0, const bf* __restrict__ B1,
              const float* __restrict__ bias, int K, int mode,
              float* __restrict__ Cp, float* __restrict__ Oh){
    extern __shared__ char smraw[];
    uint32_t sbase = s2u(smraw);
    int t = threadIdx.x, lane = t & 31, wid = t >> 5;
    int wm = wid & 1, wn = wid >> 1;
    int m0 = blockIdx.y * 128, n0 = blockIdx.x * 128;
    int z = blockIdx.z, nz = gridDim.z;
    int kslice = K / nz, kbase = z * kslice, nch = kslice / 16;

    const bf* src[4] = {A0 + (size_t)m0*K, A1 + (size_t)m0*K,
                        B0 + (size_t)n0*K, B1 + (size_t)n0*K};

    float acc[4][4][4];
#pragma unroll
    for (int i = 0; i < 4; i++)
#pragma unroll
        for (int j = 0; j < 4; j++)
#pragma unroll
            for (int k = 0; k < 4; k++) acc[i][j][k] = 0.f;

    auto loadChunk = [&](uint32_t stb, int ko){
#pragma unroll
        for (int i = 0; i < 4; i++){
            int v = t + i*256;
            int tile = v >> 8, idx = v & 255;
            int row = idx >> 1, grp = idx & 1;
            cpa16(stb + tile*TILEB + row*TP + grp*16,
                  src[tile] + (size_t)row*K + ko + grp*8);
        }
        asm volatile("cp.async.commit_group;":::"memory");
    };

    loadChunk(sbase, kbase);

    uint32_t lsel = (lane & 15)*TP + (lane >> 4)*16;
    for (int c = 0; c < nch; c++){
        int buf = c & 1;
        if (c + 1 < nch){
            loadChunk(sbase + (buf^1)*BUFB, kbase + (c+1)*16);
            asm volatile("cp.async.wait_group 1;":::"memory");
        } else {
            asm volatile("cp.async.wait_group 0;":::"memory");
        }
        __syncthreads();
        uint32_t stb = sbase + buf*BUFB;
        uint32_t b0[4][2], b1[4][2];
#pragma unroll
        for (int s = 0; s < 2; s++){
#pragma unroll
            for (int jj = 0; jj < 2; jj++){
                uint32_t r[4];
                ldsm4(r, stb + (2+s)*TILEB + (wn*32 + jj*16)*TP + lsel);
                if (s == 0){
                    b0[jj*2  ][0] = r[0]; b0[jj*2  ][1] = r[2];
                    b0[jj*2+1][0] = r[1]; b0[jj*2+1][1] = r[3];
                } else {
                    b1[jj*2  ][0] = r[0]; b1[jj*2  ][1] = r[2];
                    b1[jj*2+1][0] = r[1]; b1[jj*2+1][1] = r[3];
                }
            }
        }
        uint32_t a0[4][4], a1[4][4];
#pragma unroll
        for (int i = 0; i < 4; i++){
            ldsm4(a0[i], stb + 0*TILEB + (wm*64 + i*16)*TP + lsel);
            ldsm4(a1[i], stb + 1*TILEB + (wm*64 + i*16)*TP + lsel);
        }
        // e-outer: each term is 16 independent accumulator streams
#pragma unroll
        for (int e = 0; e < 3; e++){
#pragma unroll
            for (int i = 0; i < 4; i++){
                const uint32_t* af = (e < 2) ? a0[i] : a1[i];
#pragma unroll
                for (int j = 0; j < 4; j++){
                    const uint32_t* bfr = (e == 1) ? b1[j] : b0[j];
                    mma16816(acc[i][j], af, bfr);
                }
            }
        }
        __syncthreads();
    }

    if (mode == 0){
        float* outp = Cp + (size_t)z * MPAD * HID;
#pragma unroll
        for (int i = 0; i < 4; i++){
            int mr = m0 + wm*64 + i*16 + (lane >> 2);
#pragma unroll
            for (int j = 0; j < 4; j++){
                int nc = n0 + wn*32 + j*8 + (lane & 3)*2;
                *(float2*)(outp + (size_t)mr*HID + nc) = make_float2(acc[i][j][0], acc[i][j][1]);
                *(float2*)(outp + (size_t)(mr+8)*HID + nc) = make_float2(acc[i][j][2], acc[i][j][3]);
            }
        }
    } else {
#pragma unroll
        for (int i = 0; i < 4; i++){
#pragma unroll
            for (int j = 0; j < 4; j++){
                int nc = n0 + wn*32 + j*8 + (lane & 3)*2;
#pragma unroll
                for (int h = 0; h < 2; h++){
                    int m = m0 + wm*64 + i*16 + (lane >> 2) + h*8;
                    if (m < NPROP){
                        if (nc < 105)   Oh[(size_t)m*105 + nc]   = acc[i][j][h*2]   + bias[nc];
                        if (nc+1 < 105) Oh[(size_t)m*105 + nc+1] = acc[i][j][h*2+1] + bias[nc+1];
                    }
                }
            }
        }
    }
}

// ---------------- sum 4 split-K partials + bias + relu + split2 ----------------
__global__ void fixup_split(const float* __restrict__ p, const float* __restrict__ bias,
                            bf* __restrict__ o0, bf* __restrict__ o1){
    int i = blockIdx.x*256 + threadIdx.x;
    const int N = MPAD*HID;
    float v = fmaxf(p[i] + p[N + i] + p[2*N + i] + p[3*N + i] + bias[i & (HID-1)], 0.f);
    bf h0, h1; split2(v, h0, h1);
    o0[i] = h0; o1[i] = h1;
}

// ---------------- softmax + decode -> class-major candidates ----------------
__global__ void postproc_kernel(const float* __restrict__ rois){
    int m = blockIdx.x*128 + threadIdx.x;
    if (m >= NPROP) return;
    const float* h = g_head + (size_t)m*105;
    float lg[21], mx = -INFINITY;
#pragma unroll
    for (int c = 0; c < 21; c++){ lg[c] = h[c]; mx = fmaxf(mx, lg[c]); }
    float sum = 0.f;
#pragma unroll
    for (int c = 0; c < 21; c++){ lg[c] = expf(lg[c] - mx); sum += lg[c]; }
    float inv = 1.0f / sum;
    float4 r = ((const float4*)rois)[m];
    float w = r.z - r.x, hh = r.w - r.y;
    float cx = r.x + 0.5f*w, cy = r.y + 0.5f*hh;
#pragma unroll
    for (int c = 1; c < 21; c++){
        float sc = lg[c]*inv;
        float dx = h[21 + c*4 + 0], dy = h[21 + c*4 + 1];
        float dw = h[21 + c*4 + 2], dh = h[21 + c*4 + 3];
        float pcx = dx*w + cx, pcy = dy*hh + cy;
        float pw = expf(dw)*w, ph2 = expf(dh)*hh;
        float x1 = pcx - 0.5f*pw, y1 = pcy - 0.5f*ph2;
        float x2 = pcx + 0.5f*pw, y2 = pcy + 0.5f*ph2;
        int i = (c-1)*1000 + m;
        g_boxesC[i] = make_float4(x1, y1, x2, y2);
        float off = (float)c * 10000.0f;
        g_boxoffC[i] = make_float4(x1 + off, y1 + off, x2 + off, y2 + off);
        g_candC[i] = (sc > 0.05f) ? sc : -1.0f;
    }
}

// ---------------- per-class greedy NMS, capped at MAXDET picks ----------------
__global__ void class_nms(){
    int cz = blockIdx.x, t = threadIdx.x;
    __shared__ float sc[1000];
    __shared__ float4 bx[1000];
    __shared__ float rv[8]; __shared__ int ri[8];
    __shared__ float4 pbS; __shared__ int s_stop, s_nk;
    for (int i = t; i < 1000; i += 256){
        sc[i] = g_candC[cz*1000 + i];
        bx[i] = g_boxoffC[cz*1000 + i];
    }
    if (t == 0){ s_stop = 0; s_nk = 0; }
    __syncthreads();
    for (int it = 0; it < MAXDET; it++){
        float bv = -INFINITY; int bi = 1 << 30;
#pragma unroll
        for (int w = 0; w < 4; w++){
            int i = t + (w << 8);
            if (i < 1000){
                float v = sc[i];
                if (v > bv || (v == bv && i < bi)){ bv = v; bi = i; }
            }
        }
#pragma unroll
        for (int o = 16; o; o >>= 1){
            float ov = __shfl_down_sync(~0u, bv, o);
            int oi = __shfl_down_sync(~0u, bi, o);
            if (ov > bv || (ov == bv && oi < bi)){ bv = ov; bi = oi; }
        }
        if ((t & 31) == 0){ rv[t >> 5] = bv; ri[t >> 5] = bi; }
        __syncthreads();
        if (t == 0){
            float mb = -INFINITY; int mi = 1 << 30;
#pragma unroll
            for (int k = 0; k < 8; k++)
                if (rv[k] > mb || (rv[k] == mb && ri[k] < mi)){ mb = rv[k]; mi = ri[k]; }
            if (mb > 0.05f){
                int slot = s_nk++;
                g_svS[cz*MAXDET + slot] = mb;
                g_svOrd[cz*MAXDET + slot] = mi*20 + cz;
                g_svBox[cz*MAXDET + slot] = g_boxesC[cz*1000 + mi];
                pbS = bx[mi];
            } else s_stop = 1;
        }
        __syncthreads();
        if (s_stop) break;
        float4 p = pbS;
        float pa = (p.z - p.x) * (p.w - p.y);
#pragma unroll
        for (int w = 0; w < 4; w++){
            int i = t + (w << 8);
            if (i < 1000){
                float v = sc[i];
                if (v > -INFINITY){
                    float4 b = bx[i];
                    float ix1 = fmaxf(p.x, b.x), iy1 = fmaxf(p.y, b.y);
                    float ix2 = fminf(p.z, b.z), iy2 = fminf(p.w, b.w);
                    float inter = fmaxf(ix2 - ix1, 0.f) * fmaxf(iy2 - iy1, 0.f);
                    float A = (b.z - b.x) * (b.w - b.y);
                    if (inter / (pa + A - inter + 1e-9f) > 0.5f) sc[i] = -INFINITY;
                }
            }
        }
        __syncthreads();
    }
    if (t == 0) g_svCnt[cz] = s_nk;
}

// ---------------- 20-way sorted merge -> top-100 (1 warp) ----------------
__global__ void merge_top(float* __restrict__ out){
    int lane = threadIdx.x;
    int head = 0;
    int cnt = (lane < 20) ? g_svCnt[lane] : 0;
    for (int it = 0; it < MAXDET; it++){
        float v; int ord;
        if (lane < 20 && head < cnt){
            v = g_svS[lane*MAXDET + head];
            ord = g_svOrd[lane*MAXDET + head];
        } else { v = -INFINITY; ord = 0x7fffffff; }
        float bv = v; int bord = ord, bl = lane;
#pragma unroll
        for (int o = 16; o; o >>= 1){
            float ov = __shfl_down_sync(~0u, bv, o);
            int oo = __shfl_down_sync(~0u, bord, o);
            int ol = __shfl_down_sync(~0u, bl, o);
            if (ov > bv || (ov == bv && oo < bord)){ bv = ov; bord = oo; bl = ol; }
        }
        bl = __shfl_sync(~0u, bl, 0);
        bv = __shfl_sync(~0u, bv, 0);
        if (bv <= -INFINITY) break;
        if (lane == bl){
            float4 b = g_svBox[lane*MAXDET + head];
            out[it*4+0] = b.x; out[it*4+1] = b.y; out[it*4+2] = b.z; out[it*4+3] = b.w;
            out[400 + it] = bv;
            out[500 + it] = (float)(lane + 1);
            head++;
        }
        __syncwarp();
    }
}

__global__ void zero_out(float* out, int n){
    int i = blockIdx.x*256 + threadIdx.x;
    if (i < n) out[i] = 0.f;
}

// ---------------- launcher ----------------
extern "C" void kernel_launch(void* const* d_in, const int* in_sizes, int n_in,
                              void* d_out, int out_size){
    const float* fm = (const float*)d_in[0];
    const float* pr = (const float*)d_in[1];
    const float* w1 = (const float*)d_in[2];
    const float* b1 = (const float*)d_in[3];
    const float* w2 = (const float*)d_in[4];
    const float* b2 = (const float*)d_in[5];
    const float* wc = (const float*)d_in[6];
    const float* bc = (const float*)d_in[7];
    const float* wb = (const float*)d_in[8];
    const float* bb = (const float*)d_in[9];
    float* out = (float*)d_out;

    bf *A0,*A1,*W10,*W11,*X1a,*X1b,*W20,*W21,*X2a,*X2b,*WH0,*WH1;
    float *bh, *head, *part;
    cudaGetSymbolAddress((void**)&A0, g_A0);   cudaGetSymbolAddress((void**)&A1, g_A1);
    cudaGetSymbolAddress((void**)&W10, g_W10); cudaGetSymbolAddress((void**)&W11, g_W11);
    cudaGetSymbolAddress((void**)&X1a, g_X1a); cudaGetSymbolAddress((void**)&X1b, g_X1b);
    cudaGetSymbolAddress((void**)&W20, g_W20); cudaGetSymbolAddress((void**)&W21, g_W21);
    cudaGetSymbolAddress((void**)&X2a, g_X2a); cudaGetSymbolAddress((void**)&X2b, g_X2b);
    cudaGetSymbolAddress((void**)&WH0, g_WH0); cudaGetSymbolAddress((void**)&WH1, g_WH1);
    cudaGetSymbolAddress((void**)&bh, g_bh);   cudaGetSymbolAddress((void**)&head, g_head);
    cudaGetSymbolAddress((void**)&part, g_part);

    cudaFuncSetAttribute(gemm_mma, cudaFuncAttributeMaxDynamicSharedMemorySize, GSMEM);

    prep_kernel<<<16200, 256>>>(w1, fm, w2, wc, bc, wb, bb);          // 1
    roi_align_kernel<<<NPROP, 256>>>(pr);                             // 2
    zero_out<<<(out_size + 255) / 256, 256>>>(out, out_size);         // 3
    gemm_mma<<<dim3(8, 8, 4), 256, GSMEM>>>(A0, A1, W10, W11,         // 4 (profiled)
                                            nullptr, K1, 0, part, nullptr);
    fixup_split<<<MPAD*HID/256, 256>>>(part, b1, X1a, X1b);           // 5
    gemm_mma<<<dim3(8, 8, 4), 256, GSMEM>>>(X1a, X1b, W20, W21,       // 6
                                            nullptr, HID, 0, part, nullptr);
    fixup_split<<<MPAD*HID/256, 256>>>(part, b2, X2a, X2b);           // 7
    gemm_mma<<<dim3(1, 8, 1), 256, GSMEM>>>(X2a, X2b, WH0, WH1,       // 8
                                            bh, HID, 1, nullptr, head);
    postproc_kernel<<<8, 128>>>(pr);                                  // 9
    class_nms<<<20, 256>>>();                                         // 10
    merge_top<<<1, 32>>>(out);                                        // 11
}

// round 15
// speedup vs baseline: 1.9713x; 1.0620x over previous
#include <cuda_runtime.h>
#include <cuda_bf16.h>
#include <math.h>
#include <stdint.h>

#define NPROP 1000
#define MPAD  1024
#define FM_HW 10000
#define K1    12544
#define HID   1024
#define MAXDET 100

typedef __nv_bfloat16 bf;
typedef unsigned long long ull;

// ---------------- scratch ----------------
__device__ float g_fmT[FM_HW * 256];
__device__ bf g_A0[MPAD*K1], g_A1[MPAD*K1];
__device__ bf g_W10[HID*K1], g_W11[HID*K1];
__device__ bf g_X1a[MPAD*HID], g_X1b[MPAD*HID];
__device__ bf g_W20[HID*HID], g_W21[HID*HID];
__device__ bf g_X2a[MPAD*HID], g_X2b[MPAD*HID];
__device__ bf g_WH0[128*HID], g_WH1[128*HID];
__device__ float g_bh[128];
__device__ float g_part[4 * MPAD * HID];
__device__ float g_head[NPROP * 105];
__device__ float  g_candC[20*1000];
__device__ float4 g_boxesC[20*1000], g_boxoffC[20*1000];
__device__ float  g_svS[20*MAXDET];
__device__ int    g_svOrd[20*MAXDET];
__device__ float4 g_svBox[20*MAXDET];
__device__ int    g_svCnt[20];

// ---------------- PTX helpers ----------------
__device__ __forceinline__ uint32_t s2u(const void* p){
    uint32_t a; asm("{ .reg .u64 t; cvta.to.shared.u64 t, %1; cvt.u32.u64 %0, t; }":"=r"(a):"l"(p)); return a;
}
__device__ __forceinline__ void cpa16(uint32_t s, const void* g){
    asm volatile("cp.async.cg.shared.global [%0], [%1], 16;"::"r"(s),"l"(g):"memory");
}
__device__ __forceinline__ void ldsm4(uint32_t* r, uint32_t addr){
    asm volatile("ldmatrix.sync.aligned.m8n8.x4.shared.b16 {%0,%1,%2,%3}, [%4];"
        :"=r"(r[0]),"=r"(r[1]),"=r"(r[2]),"=r"(r[3]):"r"(addr));
}
__device__ __forceinline__ void mma16816(float* d, const uint32_t* a, const uint32_t* b){
    asm volatile("mma.sync.aligned.m16n8k16.row.col.f32.bf16.bf16.f32 "
        "{%0,%1,%2,%3}, {%4,%5,%6,%7}, {%8,%9}, {%0,%1,%2,%3};"
        :"+f"(d[0]),"+f"(d[1]),"+f"(d[2]),"+f"(d[3])
        :"r"(a[0]),"r"(a[1]),"r"(a[2]),"r"(a[3]),"r"(b[0]),"r"(b[1]));
}
__device__ __forceinline__ void split2(float v, bf& b0, bf& b1){
    b0 = __float2bfloat16(v);
    b1 = __float2bfloat16(v - __bfloat162float(b0));
}

// ---------------- prep part 1: w1 transpose+permute+split ----------------
__global__ void prep_w1(const float* __restrict__ w1){
    __shared__ float tl[32][33];
    int b = blockIdx.x, t = threadIdx.x;
    int tx = t & 31, ty = t >> 5;
    int bx = b % 392, by = b / 392;
    int cell = bx >> 3, c0 = (bx & 7) * 32;
    int h0 = by * 32;
#pragma unroll
    for (int j = 0; j < 32; j += 8){
        int c = c0 + ty + j;
        tl[ty+j][tx] = w1[(size_t)(c * 49 + cell) * HID + h0 + tx];
    }
    __syncthreads();
#pragma unroll
    for (int j = 0; j < 32; j += 8){
        int h = h0 + ty + j;
        float v = tl[tx][ty+j];
        size_t o = (size_t)h * K1 + cell*256 + c0 + tx;
        bf h0b, h1b; split2(v, h0b, h1b);
        g_W10[o] = h0b; g_W11[o] = h1b;
    }
}

// ---------------- prep part 2: fm transpose, w2 transpose, heads weights -------
__global__ void prep_rest(const float* __restrict__ fm, const float* __restrict__ w2,
                          const float* __restrict__ wc, const float* __restrict__ bc,
                          const float* __restrict__ wb, const float* __restrict__ bb){
    __shared__ float tl[32][33];
    int b = blockIdx.x, t = threadIdx.x;
    int tx = t & 31, ty = t >> 5;
    if (b < 2504){
        int hw0 = (b % 313) * 32, c0 = (b / 313) * 32;
#pragma unroll
        for (int j = 0; j < 32; j += 8){
            int hw = hw0 + tx;
            tl[ty+j][tx] = (hw < FM_HW) ? fm[(c0+ty+j)*FM_HW + hw] : 0.f;
        }
        __syncthreads();
#pragma unroll
        for (int j = 0; j < 32; j += 8){
            int hw = hw0 + ty + j;
            if (hw < FM_HW) g_fmT[hw*256 + c0 + tx] = tl[tx][ty+j];
        }
    } else if (b < 3528){
        int r = b - 2504;
        int c0 = (r & 31) * 32, r0 = (r >> 5) * 32;
#pragma unroll
        for (int j = 0; j < 32; j += 8)
            tl[ty+j][tx] = w2[(size_t)(r0+ty+j)*HID + c0 + tx];
        __syncthreads();
#pragma unroll
        for (int j = 0; j < 32; j += 8){
            float v = tl[tx][ty+j];
            size_t o = (size_t)(c0+ty+j)*HID + r0 + tx;
            bf h0, h1; split2(v, h0, h1);
            g_W20[o] = h0; g_W21[o] = h1;
        }
    } else {
        int h = b - 3528;
        for (int k = t; k < HID; k += 256){
            float v = (h < 21) ? wc[k*21 + h] : ((h < 105) ? wb[k*84 + (h-21)] : 0.f);
            bf h0, h1; split2(v, h0, h1);
            size_t o = (size_t)h*HID + k;
            g_WH0[o] = h0; g_WH1[o] = h1;
        }
        if (t == 0)
            g_bh[h] = (h < 21) ? bc[h] : ((h < 105) ? bb[h-21] : 0.f);
    }
}

// ---------------- ROI align -> split-bf16 A (512 threads) ----------------
__global__ void roi_align_kernel(const float* __restrict__ rois){
    int n = blockIdx.x, t = threadIdx.x;
    int tc = t & 63, cg = t >> 6;                 // 8 cell groups
    float4 r = ((const float4*)rois)[n];
    float b0 = r.x*0.125f - 0.5f, b1 = r.y*0.125f - 0.5f;
    float bw = (r.z*0.125f - 0.5f - b0) / 7.0f, bh = (r.w*0.125f - 0.5f - b1) / 7.0f;
    __shared__ int sx0[14], sx1[14], sy0[14], sy1[14];
    __shared__ float swx0[14], swx1[14], swy0[14], swy1[14], svx[14], svy[14];
    if (t < 14){
        int p = t >> 1, s = t & 1;
        float off = (float)p + ((float)s + 0.5f)*0.5f;
        float v = b0 + off*bw;
        svx[t] = (v >= -1.f && v <= 100.f) ? 1.f : 0.f;
        v = fminf(fmaxf(v, 0.f), 99.f);
        float v0 = floorf(v); int i0 = (int)v0;
        sx0[t] = i0; sx1[t] = min(i0+1, 99); swx1[t] = v - v0; swx0[t] = 1.f - (v - v0);
        v = b1 + off*bh;
        svy[t] = (v >= -1.f && v <= 100.f) ? 1.f : 0.f;
        v = fminf(fmaxf(v, 0.f), 99.f);
        v0 = floorf(v); i0 = (int)v0;
        sy0[t] = i0; sy1[t] = min(i0+1, 99); swy1[t] = v - v0; swy0[t] = 1.f - (v - v0);
    }
    __syncthreads();
    const float4* fmT4 = (const float4*)g_fmT;
    bf* a0p = g_A0 + (size_t)n*K1;
    bf* a1p = g_A1 + (size_t)n*K1;
    for (int cell = cg; cell < 49; cell += 8){
        int ph = cell / 7, pw = cell - ph*7;
        float ax = 0, ay = 0, az = 0, aw = 0;
#pragma unroll
        for (int sy = 0; sy < 2; sy++){
            int j = ph*2 + sy;
            int y0 = sy0[j], y1 = sy1[j];
            float wy0 = swy0[j], wy1 = swy1[j], vy = svy[j];
#pragma unroll
            for (int sx = 0; sx < 2; sx++){
                int k = pw*2 + sx;
                if (vy * svx[k] != 0.f){
                    int x0 = sx0[k], x1 = sx1[k];
                    float w00 = wy0*swx0[k], w01 = wy0*swx1[k], w10 = wy1*swx0[k], w11 = wy1*swx1[k];
                    float4 f00 = fmT4[(y0*100+x0)*64+tc], f01 = fmT4[(y0*100+x1)*64+tc];
                    float4 f10 = fmT4[(y1*100+x0)*64+tc], f11 = fmT4[(y1*100+x1)*64+tc];
                    ax += w00*f00.x + w01*f01.x + w10*f10.x + w11*f11.x;
                    ay += w00*f00.y + w01*f01.y + w10*f10.y + w11*f11.y;
                    az += w00*f00.z + w01*f01.z + w10*f10.z + w11*f11.z;
                    aw += w00*f00.w + w01*f01.w + w10*f10.w + w11*f11.w;
                }
            }
        }
        float vals[4] = {ax*0.25f, ay*0.25f, az*0.25f, aw*0.25f};
        bf p0[4], p1[4];
#pragma unroll
        for (int i = 0; i < 4; i++) split2(vals[i], p0[i], p1[i]);
        int base = cell*256 + tc*4;
        *(ull*)(a0p + base) = *(ull*)p0;
        *(ull*)(a1p + base) = *(ull*)p1;
    }
}

// ---------------- mma.sync bf16 GEMM (split-2, 3 terms), R11 config ------------
#define TP    48
#define TILEB (128*TP)           // 6144
#define BUFB  (4*TILEB)          // 24576
#define GSMEM (2*BUFB)           // 49152

__global__ __launch_bounds__(256, 2)
void gemm_mma(const bf* __restrict__ A0, const bf* __restrict__ A1,
              const bf* __restrict__ B0, const bf* __restrict__ B1,
              int K, float* __restrict__ Cp){
    extern __shared__ char smraw[];
    uint32_t sbase = s2u(smraw);
    int t = threadIdx.x, lane = t & 31, wid = t >> 5;
    int wm = wid & 1, wn = wid >> 1;
    int m0 = blockIdx.y * 128, n0 = blockIdx.x * 128;
    int z = blockIdx.z, nz = gridDim.z;
    int kslice = K / nz, kbase = z * kslice, nch = kslice / 16;

    const bf* src[4] = {A0 + (size_t)m0*K, A1 + (size_t)m0*K,
                        B0 + (size_t)n0*K, B1 + (size_t)n0*K};

    float acc[4][4][4];
#pragma unroll
    for (int i = 0; i < 4; i++)
#pragma unroll
        for (int j = 0; j < 4; j++)
#pragma unroll
            for (int k = 0; k < 4; k++) acc[i][j][k] = 0.f;

    auto loadChunk = [&](uint32_t stb, int ko){
#pragma unroll
        for (int i = 0; i < 4; i++){
            int v = t + i*256;
            int tile = v >> 8, idx = v & 255;
            int row = idx >> 1, grp = idx & 1;
            cpa16(stb + tile*TILEB + row*TP + grp*16,
                  src[tile] + (size_t)row*K + ko + grp*8);
        }
        asm volatile("cp.async.commit_group;":::"memory");
    };

    loadChunk(sbase, kbase);

    uint32_t lsel = (lane & 15)*TP + (lane >> 4)*16;
    for (int c = 0; c < nch; c++){
        int buf = c & 1;
        if (c + 1 < nch){
            loadChunk(sbase + (buf^1)*BUFB, kbase + (c+1)*16);
            asm volatile("cp.async.wait_group 1;":::"memory");
        } else {
            asm volatile("cp.async.wait_group 0;":::"memory");
        }
        __syncthreads();
        uint32_t stb = sbase + buf*BUFB;
        uint32_t b0[4][2], b1[4][2];
#pragma unroll
        for (int s = 0; s < 2; s++){
#pragma unroll
            for (int jj = 0; jj < 2; jj++){
                uint32_t r[4];
                ldsm4(r, stb + (2+s)*TILEB + (wn*32 + jj*16)*TP + lsel);
                if (s == 0){
                    b0[jj*2  ][0] = r[0]; b0[jj*2  ][1] = r[2];
                    b0[jj*2+1][0] = r[1]; b0[jj*2+1][1] = r[3];
                } else {
                    b1[jj*2  ][0] = r[0]; b1[jj*2  ][1] = r[2];
                    b1[jj*2+1][0] = r[1]; b1[jj*2+1][1] = r[3];
                }
            }
        }
#pragma unroll
        for (int i = 0; i < 4; i++){
            uint32_t a0[4], a1[4];
            ldsm4(a0, stb + 0*TILEB + (wm*64 + i*16)*TP + lsel);
            ldsm4(a1, stb + 1*TILEB + (wm*64 + i*16)*TP + lsel);
#pragma unroll
            for (int j = 0; j < 4; j++){
                mma16816(acc[i][j], a0, b0[j]);
                mma16816(acc[i][j], a0, b1[j]);
                mma16816(acc[i][j], a1, b0[j]);
            }
        }
        __syncthreads();
    }

    float* outp = Cp + (size_t)z * MPAD * HID;
#pragma unroll
    for (int i = 0; i < 4; i++){
        int mr = m0 + wm*64 + i*16 + (lane >> 2);
#pragma unroll
        for (int j = 0; j < 4; j++){
            int nc = n0 + wn*32 + j*8 + (lane & 3)*2;
            *(float2*)(outp + (size_t)mr*HID + nc) = make_float2(acc[i][j][0], acc[i][j][1]);
            *(float2*)(outp + (size_t)(mr+8)*HID + nc) = make_float2(acc[i][j][2], acc[i][j][3]);
        }
    }
}

// ---------------- sum 4 split-K partials + bias + relu + split2 ----------------
__global__ void fixup_split(const float* __restrict__ p, const float* __restrict__ bias,
                            bf* __restrict__ o0, bf* __restrict__ o1){
    int i = blockIdx.x*256 + threadIdx.x;
    const int N = MPAD*HID;
    float v = fmaxf(p[i] + p[N + i] + p[2*N + i] + p[3*N + i] + bias[i & (HID-1)], 0.f);
    bf h0, h1; split2(v, h0, h1);
    o0[i] = h0; o1[i] = h1;
}

// ---------------- heads fixup: sum 4 partials + bias -> g_head -----------------
__global__ void fixup_heads(const float* __restrict__ p){
    int i = blockIdx.x*256 + threadIdx.x;
    if (i >= NPROP*105) return;
    int m = i / 105, n = i - m*105;
    const int N = MPAD*HID;
    size_t o = (size_t)m*HID + n;
    g_head[i] = p[o] + p[N + o] + p[2*N + o] + p[3*N + o] + g_bh[n];
}

// ---------------- softmax + decode -> class-major candidates ----------------
__global__ void postproc_kernel(const float* __restrict__ rois){
    int m = blockIdx.x*128 + threadIdx.x;
    if (m >= NPROP) return;
    const float* h = g_head + (size_t)m*105;
    float lg[21], mx = -INFINITY;
#pragma unroll
    for (int c = 0; c < 21; c++){ lg[c] = h[c]; mx = fmaxf(mx, lg[c]); }
    float sum = 0.f;
#pragma unroll
    for (int c = 0; c < 21; c++){ lg[c] = expf(lg[c] - mx); sum += lg[c]; }
    float inv = 1.0f / sum;
    float4 r = ((const float4*)rois)[m];
    float w = r.z - r.x, hh = r.w - r.y;
    float cx = r.x + 0.5f*w, cy = r.y + 0.5f*hh;
#pragma unroll
    for (int c = 1; c < 21; c++){
        float sc = lg[c]*inv;
        float dx = h[21 + c*4 + 0], dy = h[21 + c*4 + 1];
        float dw = h[21 + c*4 + 2], dh = h[21 + c*4 + 3];
        float pcx = dx*w + cx, pcy = dy*hh + cy;
        float pw = expf(dw)*w, ph2 = expf(dh)*hh;
        float x1 = pcx - 0.5f*pw, y1 = pcy - 0.5f*ph2;
        float x2 = pcx + 0.5f*pw, y2 = pcy + 0.5f*ph2;
        int i = (c-1)*1000 + m;
        g_boxesC[i] = make_float4(x1, y1, x2, y2);
        float off = (float)c * 10000.0f;
        g_boxoffC[i] = make_float4(x1 + off, y1 + off, x2 + off, y2 + off);
        g_candC[i] = (sc > 0.05f) ? sc : -1.0f;
    }
}

// ---------------- per-class greedy NMS, capped at MAXDET picks ----------------
__global__ void class_nms(){
    int cz = blockIdx.x, t = threadIdx.x;
    __shared__ float sc[1000];
    __shared__ float4 bx[1000];
    __shared__ float rv[8]; __shared__ int ri[8];
    __shared__ float4 pbS; __shared__ int s_stop, s_nk;
    for (int i = t; i < 1000; i += 256){
        sc[i] = g_candC[cz*1000 + i];
        bx[i] = g_boxoffC[cz*1000 + i];
    }
    if (t == 0){ s_stop = 0; s_nk = 0; }
    __syncthreads();
    for (int it = 0; it < MAXDET; it++){
        float bv = -INFINITY; int bi = 1 << 30;
#pragma unroll
        for (int w = 0; w < 4; w++){
            int i = t + (w << 8);
            if (i < 1000){
                float v = sc[i];
                if (v > bv || (v == bv && i < bi)){ bv = v; bi = i; }
            }
        }
#pragma unroll
        for (int o = 16; o; o >>= 1){
            float ov = __shfl_down_sync(~0u, bv, o);
            int oi = __shfl_down_sync(~0u, bi, o);
            if (ov > bv || (ov == bv && oi < bi)){ bv = ov; bi = oi; }
        }
        if ((t & 31) == 0){ rv[t >> 5] = bv; ri[t >> 5] = bi; }
        __syncthreads();
        if (t == 0){
            float mb = -INFINITY; int mi = 1 << 30;
#pragma unroll
            for (int k = 0; k < 8; k++)
                if (rv[k] > mb || (rv[k] == mb && ri[k] < mi)){ mb = rv[k]; mi = ri[k]; }
            if (mb > 0.05f){
                int slot = s_nk++;
                g_svS[cz*MAXDET + slot] = mb;
                g_svOrd[cz*MAXDET + slot] = mi*20 + cz;
                g_svBox[cz*MAXDET + slot] = g_boxesC[cz*1000 + mi];
                pbS = bx[mi];
            } else s_stop = 1;
        }
        __syncthreads();
        if (s_stop) break;
        float4 p = pbS;
        float pa = (p.z - p.x) * (p.w - p.y);
#pragma unroll
        for (int w = 0; w < 4; w++){
            int i = t + (w << 8);
            if (i < 1000){
                float v = sc[i];
                if (v > -INFINITY){
                    float4 b = bx[i];
                    float ix1 = fmaxf(p.x, b.x), iy1 = fmaxf(p.y, b.y);
                    float ix2 = fminf(p.z, b.z), iy2 = fminf(p.w, b.w);
                    float inter = fmaxf(ix2 - ix1, 0.f) * fmaxf(iy2 - iy1, 0.f);
                    float A = (b.z - b.x) * (b.w - b.y);
                    if (inter / (pa + A - inter + 1e-9f) > 0.5f) sc[i] = -INFINITY;
                }
            }
        }
        __syncthreads();
    }
    if (t == 0) g_svCnt[cz] = s_nk;
}

// ---------------- 20-way sorted merge -> top-100 (1 warp) ----------------
__global__ void merge_top(float* __restrict__ out){
    int lane = threadIdx.x;
    int head = 0;
    int cnt = (lane < 20) ? g_svCnt[lane] : 0;
    for (int it = 0; it < MAXDET; it++){
        float v; int ord;
        if (lane < 20 && head < cnt){
            v = g_svS[lane*MAXDET + head];
            ord = g_svOrd[lane*MAXDET + head];
        } else { v = -INFINITY; ord = 0x7fffffff; }
        float bv = v; int bord = ord, bl = lane;
#pragma unroll
        for (int o = 16; o; o >>= 1){
            float ov = __shfl_down_sync(~0u, bv, o);
            int oo = __shfl_down_sync(~0u, bord, o);
            int ol = __shfl_down_sync(~0u, bl, o);
            if (ov > bv || (ov == bv && oo < bord)){ bv = ov; bord = oo; bl = ol; }
        }
        bl = __shfl_sync(~0u, bl, 0);
        bv = __shfl_sync(~0u, bv, 0);
        if (bv <= -INFINITY) break;
        if (lane == bl){
            float4 b = g_svBox[lane*MAXDET + head];
            out[it*4+0] = b.x; out[it*4+1] = b.y; out[it*4+2] = b.z; out[it*4+3] = b.w;
            out[400 + it] = bv;
            out[500 + it] = (float)(lane + 1);
            head++;
        }
        __syncwarp();
    }
}

__global__ void zero_out(float* out, int n){
    int i = blockIdx.x*256 + threadIdx.x;
    if (i < n) out[i] = 0.f;
}

// ---------------- launcher ----------------
extern "C" void kernel_launch(void* const* d_in, const int* in_sizes, int n_in,
                              void* d_out, int out_size){
    const float* fm = (const float*)d_in[0];
    const float* pr = (const float*)d_in[1];
    const float* w1 = (const float*)d_in[2];
    const float* b1 = (const float*)d_in[3];
    const float* w2 = (const float*)d_in[4];
    const float* b2 = (const float*)d_in[5];
    const float* wc = (const float*)d_in[6];
    const float* bc = (const float*)d_in[7];
    const float* wb = (const float*)d_in[8];
    const float* bb = (const float*)d_in[9];
    float* out = (float*)d_out;

    bf *A0,*A1,*W10,*W11,*X1a,*X1b,*W20,*W21,*X2a,*X2b,*WH0,*WH1;
    float *part;
    cudaGetSymbolAddress((void**)&A0, g_A0);   cudaGetSymbolAddress((void**)&A1, g_A1);
    cudaGetSymbolAddress((void**)&W10, g_W10); cudaGetSymbolAddress((void**)&W11, g_W11);
    cudaGetSymbolAddress((void**)&X1a, g_X1a); cudaGetSymbolAddress((void**)&X1b, g_X1b);
    cudaGetSymbolAddress((void**)&W20, g_W20); cudaGetSymbolAddress((void**)&W21, g_W21);
    cudaGetSymbolAddress((void**)&X2a, g_X2a); cudaGetSymbolAddress((void**)&X2b, g_X2b);
    cudaGetSymbolAddress((void**)&WH0, g_WH0); cudaGetSymbolAddress((void**)&WH1, g_WH1);
    cudaGetSymbolAddress((void**)&part, g_part);

    cudaFuncSetAttribute(gemm_mma, cudaFuncAttributeMaxDynamicSharedMemorySize, GSMEM);

    prep_w1<<<12544, 256>>>(w1);                                      // 1
    prep_rest<<<3656, 256>>>(fm, w2, wc, bc, wb, bb);                 // 2
    zero_out<<<(out_size + 255) / 256, 256>>>(out, out_size);         // 3
    roi_align_kernel<<<NPROP, 512>>>(pr);                             // 4 (profiled)
    gemm_mma<<<dim3(8, 8, 4), 256, GSMEM>>>(A0, A1, W10, W11, K1, part);     // 5
    fixup_split<<<MPAD*HID/256, 256>>>(part, b1, X1a, X1b);           // 6
    gemm_mma<<<dim3(8, 8, 4), 256, GSMEM>>>(X1a, X1b, W20, W21, HID, part);  // 7
    fixup_split<<<MPAD*HID/256, 256>>>(part, b2, X2a, X2b);           // 8
    gemm_mma<<<dim3(1, 8, 4), 256, GSMEM>>>(X2a, X2b, WH0, WH1, HID, part);  // 9
    fixup_heads<<<(NPROP*105 + 255) / 256, 256>>>(part);              // 10
    postproc_kernel<<<8, 128>>>(pr);                                  // 11
    class_nms<<<20, 256>>>();                                         // 12
    merge_top<<<1, 32>>>(out);                                        // 13
}